// round 13
// baseline (speedup 1.0000x reference)
#include <cuda_runtime.h>
#include <cuda_bf16.h>
#include <cstdint>

#define NN   100000
#define FIN  512
#define H1   8
#define D1   64      // H1*C1
#define C2   10
#define EMAXSZ 1700000
#define KSTEPS 32    // 512 / 16

// ---------------- scratch (no allocs allowed) ----------------
__device__ float g_h1 [NN * D1];     // layer1 features   25.6 MB
__device__ float g_al1[NN * H1];
__device__ float g_ar1[NN * H1];
__device__ float g_z2 [NN * C2];
__device__ float g_al2[NN];
__device__ float g_ar2[NN];
// B fragments interleaved [hi0,hi1,lo0,lo1] per lane: one uint4 per (ks,tile,lane)
__device__ uint32_t g_bhl[KSTEPS * 8 * 128];
// sorted-by-dst edge structures
__device__ int   g_cnt [NN];         // zero at entry (module init; scan23 restores)
__device__ int   g_tmp [NN];
__device__ int   g_bsum[128];
__device__ int   g_off [NN + 1];
__device__ int   g_pos [NN];
__device__ int   g_esrc[EMAXSZ];

// ---------------- helpers ----------------
__device__ __forceinline__ float lrelu(float x) { return x > 0.f ? x : 0.2f * x; }

__device__ __forceinline__ float fast_exp(float x) {
    float t = x * 1.4426950408889634f;
    t = fminf(fmaxf(t, -126.f), 126.f);
    float fi = floorf(t);
    float f  = t - fi;
    int   i  = (int)fi;
    float p = 1.5403530e-4f;
    p = fmaf(p, f, 1.3333558e-3f);
    p = fmaf(p, f, 9.6181291e-3f);
    p = fmaf(p, f, 5.5504109e-2f);
    p = fmaf(p, f, 2.4022651e-1f);
    p = fmaf(p, f, 6.9314718e-1f);
    p = fmaf(p, f, 1.0f);
    return __uint_as_float(__float_as_uint(p) + ((unsigned)i << 23));
}

__device__ __forceinline__ float elu1(float x) {
    return x > 0.f ? x : fast_exp(fmaxf(x, -80.f)) - 1.f;
}

__device__ __forceinline__ uint32_t pkbf2(float a, float b) {
    __nv_bfloat162 t = __floats2bfloat162_rn(a, b);
    return *(uint32_t*)&t;
}
__device__ __forceinline__ float bf2f(float v) {
    return __bfloat162float(__float2bfloat16_rn(v));
}

// m16n8k16 row.col bf16 -> f32 accum
__device__ __forceinline__ void mma16816(float* c, const uint32_t* a,
                                         uint32_t b0, uint32_t b1) {
    asm volatile(
        "mma.sync.aligned.m16n8k16.row.col.f32.bf16.bf16.f32 "
        "{%0,%1,%2,%3}, {%4,%5,%6,%7}, {%8,%9}, {%0,%1,%2,%3};"
        : "+f"(c[0]), "+f"(c[1]), "+f"(c[2]), "+f"(c[3])
        : "r"(a[0]), "r"(a[1]), "r"(a[2]), "r"(a[3]), "r"(b0), "r"(b1));
}

// ---------------- B fragment precompute (interleaved hi/lo) ----------------
__global__ void bprep_kernel(const float* __restrict__ W) {
    int id = blockIdx.x * blockDim.x + threadIdx.x;   // 8192 threads
    if (id >= KSTEPS * 8 * 32) return;
    int l  = id & 31;
    int t  = (id >> 5) & 7;
    int ks = id >> 8;
    int k0 = ks * 16, n0 = t * 8;
    int n  = n0 + (l >> 2);
    int ka = k0 + 2 * (l & 3);
    float w00 = W[(ka)     * D1 + n], w01 = W[(ka + 1) * D1 + n];
    float w08 = W[(ka + 8) * D1 + n], w09 = W[(ka + 9) * D1 + n];
    float h00 = bf2f(w00), h01 = bf2f(w01), h08 = bf2f(w08), h09 = bf2f(w09);
    int idx = (ks * 8 + t) * 128 + 4 * l;
    g_bhl[idx]     = pkbf2(w00, w01);                    // hi pair 0
    g_bhl[idx + 1] = pkbf2(w08, w09);                    // hi pair 1
    g_bhl[idx + 2] = pkbf2(w00 - h00, w01 - h01);        // lo pair 0
    g_bhl[idx + 3] = pkbf2(w08 - h08, w09 - h09);        // lo pair 1
}

// ---------------- sort pipeline (launch-ordered, no spin-waits) ----------------
__device__ __forceinline__ bool edge_sd(const int* __restrict__ src,
                                        const int* __restrict__ dst,
                                        int e, int E, int& s, int& d) {
    if (e < E) { s = src[e]; d = dst[e]; }
    else       { s = d = e - E; }
    return (unsigned)s < NN && (unsigned)d < NN;
}

__global__ void hist_kernel(const int* __restrict__ src,
                            const int* __restrict__ dst, int E) {
    int e = blockIdx.x * blockDim.x + threadIdx.x;
    if (e >= E + NN) return;
    int s, d;
    if (!edge_sd(src, dst, e, E, s, d)) return;
    atomicAdd(&g_cnt[d], 1);
}

__global__ void scan1_kernel() {
    __shared__ int sm[1024];
    int tid = threadIdx.x, i = blockIdx.x * 1024 + tid;
    int v = (i < NN) ? g_cnt[i] : 0;
    sm[tid] = v;
    __syncthreads();
#pragma unroll
    for (int off = 1; off < 1024; off <<= 1) {
        int t = (tid >= off) ? sm[tid - off] : 0;
        __syncthreads();
        sm[tid] += t;
        __syncthreads();
    }
    if (i < NN) g_tmp[i] = sm[tid];
    if (tid == 1023) g_bsum[blockIdx.x] = sm[1023];
}

// fused block-sum scan + finalize offsets; zeroes g_cnt for next call
__global__ void scan23_kernel(int nb) {
    __shared__ int sb[128];
    int b = blockIdx.x, t = threadIdx.x;
    if (t < 128) sb[t] = (t < nb) ? g_bsum[t] : 0;
    __syncthreads();
#pragma unroll
    for (int off = 1; off < 128; off <<= 1) {
        int v = (t >= off && t < 128) ? sb[t - off] : 0;
        __syncthreads();
        if (t < 128) sb[t] += v;
        __syncthreads();
    }
    int excl = (b == 0) ? 0 : sb[b - 1];
    int i = b * 1024 + t;
    if (i < NN) {
        int c    = g_cnt[i];
        int incl = g_tmp[i] + excl;
        g_off[i + 1] = incl;
        g_pos[i]     = incl - c;
        g_cnt[i]     = 0;
        if (i == 0) g_off[0] = 0;
    }
}

__global__ void scatter_kernel(const int* __restrict__ src,
                               const int* __restrict__ dst, int E) {
    int e = blockIdx.x * blockDim.x + threadIdx.x;
    if (e >= E + NN) return;
    int s, d;
    if (!edge_sd(src, dst, e, E, s, d)) return;
    int p = atomicAdd(&g_pos[d], 1);
    g_esrc[p] = s;
}

// ---------------- tensor-core GEMM (split-bf16 mma.sync, packed B) ----------------
__global__ void __launch_bounds__(256, 2)
gemm1_kernel(const float* __restrict__ x,
             const float* __restrict__ a_src, const float* __restrict__ a_dst) {
    __shared__ float s_as[64], s_ad[64];
    int tid = threadIdx.x, w = tid >> 5, l = tid & 31;
    if (tid < 64) { s_as[tid] = a_src[tid]; s_ad[tid] = a_dst[tid]; }
    __syncthreads();

    int m0   = blockIdx.x * 128 + w * 16;
    int row0 = m0 + (l >> 2);
    int row1 = row0 + 8;
    const float* xr0 = x + (size_t)(row0 < NN ? row0 : 0) * FIN + 2 * (l & 3);
    const float* xr1 = x + (size_t)(row1 < NN ? row1 : 0) * FIN + 2 * (l & 3);

    float c[8][4];
#pragma unroll
    for (int t = 0; t < 8; t++)
#pragma unroll
        for (int q = 0; q < 4; q++) c[t][q] = 0.f;

    for (int ks = 0; ks < KSTEPS; ks++) {
        int k0 = ks * 16;
        float2 v0 = *(const float2*)(xr0 + k0);
        float2 v1 = *(const float2*)(xr1 + k0);
        float2 v2 = *(const float2*)(xr0 + k0 + 8);
        float2 v3 = *(const float2*)(xr1 + k0 + 8);
        float h0x = bf2f(v0.x), h0y = bf2f(v0.y);
        float h1x = bf2f(v1.x), h1y = bf2f(v1.y);
        float h2x = bf2f(v2.x), h2y = bf2f(v2.y);
        float h3x = bf2f(v3.x), h3y = bf2f(v3.y);
        uint32_t ah[4] = { pkbf2(h0x, h0y), pkbf2(h1x, h1y),
                           pkbf2(h2x, h2y), pkbf2(h3x, h3y) };
        uint32_t al[4] = { pkbf2(v0.x - h0x, v0.y - h0y),
                           pkbf2(v1.x - h1x, v1.y - h1y),
                           pkbf2(v2.x - h2x, v2.y - h2y),
                           pkbf2(v3.x - h3x, v3.y - h3y) };
        const uint4* bq = (const uint4*)g_bhl + (ks * 8) * 32 + l;
#pragma unroll
        for (int t = 0; t < 8; t++) {
            uint4 bb = bq[t * 32];          // {hi0, hi1, lo0, lo1} one LDG.128
            mma16816(c[t], ah, bb.x, bb.y); // hi*hi
            mma16816(c[t], ah, bb.z, bb.w); // hi*lo
            mma16816(c[t], al, bb.x, bb.y); // lo*hi
        }
    }

    // epilogue: stream stores per tile
    bool ok0 = row0 < NN, ok1 = row1 < NN;
    bool w0  = (l & 3) == 0;
#pragma unroll
    for (int t = 0; t < 8; t++) {
        int col = t * 8 + 2 * (l & 3);
        if (ok0) *(float2*)&g_h1[(size_t)row0 * D1 + col] = make_float2(c[t][0], c[t][1]);
        if (ok1) *(float2*)&g_h1[(size_t)row1 * D1 + col] = make_float2(c[t][2], c[t][3]);
        float sa0 = c[t][0] * s_as[col] + c[t][1] * s_as[col + 1];
        float sd0 = c[t][0] * s_ad[col] + c[t][1] * s_ad[col + 1];
        float sa1 = c[t][2] * s_as[col] + c[t][3] * s_as[col + 1];
        float sd1 = c[t][2] * s_ad[col] + c[t][3] * s_ad[col + 1];
#pragma unroll
        for (int off = 1; off < 4; off <<= 1) {
            sa0 += __shfl_xor_sync(~0u, sa0, off);
            sd0 += __shfl_xor_sync(~0u, sd0, off);
            sa1 += __shfl_xor_sync(~0u, sa1, off);
            sd1 += __shfl_xor_sync(~0u, sd1, off);
        }
        if (w0 && ok0) { g_al1[row0 * H1 + t] = sa0; g_ar1[row0 * H1 + t] = sd0; }
        if (w0 && ok1) { g_al1[row1 * H1 + t] = sa1; g_ar1[row1 * H1 + t] = sd1; }
    }
}

// layer-1 aggregation + FUSED layer-2 node prep; 4-way MLP unroll
__global__ void agg1_kernel(const float* __restrict__ b1, const float* __restrict__ W2,
                            const float* __restrict__ as2, const float* __restrict__ ad2) {
    __shared__ float s_ex[8][256];
    int gw = (blockIdx.x * blockDim.x + threadIdx.x) >> 5;
    int w  = (threadIdx.x >> 5);
    int lane = threadIdx.x & 31;
    if (gw >= NN) return;
    int d = gw;
    int beg = g_off[d], end = g_off[d + 1];
    float4 ar0 = *(const float4*)&g_ar1[d * H1];
    float4 ar1 = *(const float4*)&g_ar1[d * H1 + 4];
    float dsum[8];
#pragma unroll
    for (int h = 0; h < 8; h++) dsum[h] = 0.f;
    float accx = 0.f, accy = 0.f;
    int hsel = lane >> 2;
    const float* h1c = g_h1 + 2 * lane;

    for (int b = beg; b < end; b += 32) {
        int n = min(32, end - b);
        int s_my = (lane < n) ? g_esrc[b + lane] : 0;
        if (lane < n) {
            float4 a0 = *(const float4*)&g_al1[s_my * H1];
            float4 a1 = *(const float4*)&g_al1[s_my * H1 + 4];
            float ex0 = fast_exp(lrelu(a0.x + ar0.x));
            float ex1 = fast_exp(lrelu(a0.y + ar0.y));
            float ex2 = fast_exp(lrelu(a0.z + ar0.z));
            float ex3 = fast_exp(lrelu(a0.w + ar0.w));
            float ex4 = fast_exp(lrelu(a1.x + ar1.x));
            float ex5 = fast_exp(lrelu(a1.y + ar1.y));
            float ex6 = fast_exp(lrelu(a1.z + ar1.z));
            float ex7 = fast_exp(lrelu(a1.w + ar1.w));
            dsum[0] += ex0; dsum[1] += ex1; dsum[2] += ex2; dsum[3] += ex3;
            dsum[4] += ex4; dsum[5] += ex5; dsum[6] += ex6; dsum[7] += ex7;
            *(float4*)&s_ex[w][lane * 8]     = make_float4(ex0, ex1, ex2, ex3);
            *(float4*)&s_ex[w][lane * 8 + 4] = make_float4(ex4, ex5, ex6, ex7);
        }
        __syncwarp();
        int j = 0;
        for (; j + 4 <= n; j += 4) {
            int s0 = __shfl_sync(~0u, s_my, j);
            int s1 = __shfl_sync(~0u, s_my, j + 1);
            int s2 = __shfl_sync(~0u, s_my, j + 2);
            int s3 = __shfl_sync(~0u, s_my, j + 3);
            float2 h0 = *(const float2*)(h1c + (size_t)s0 * D1);
            float2 h1v = *(const float2*)(h1c + (size_t)s1 * D1);
            float2 h2 = *(const float2*)(h1c + (size_t)s2 * D1);
            float2 h3 = *(const float2*)(h1c + (size_t)s3 * D1);
            float e0 = s_ex[w][(j)     * 8 + hsel];
            float e1 = s_ex[w][(j + 1) * 8 + hsel];
            float e2 = s_ex[w][(j + 2) * 8 + hsel];
            float e3 = s_ex[w][(j + 3) * 8 + hsel];
            accx = fmaf(h0.x, e0, accx); accy = fmaf(h0.y, e0, accy);
            accx = fmaf(h1v.x, e1, accx); accy = fmaf(h1v.y, e1, accy);
            accx = fmaf(h2.x, e2, accx); accy = fmaf(h2.y, e2, accy);
            accx = fmaf(h3.x, e3, accx); accy = fmaf(h3.y, e3, accy);
        }
        for (; j < n; j++) {
            int s = __shfl_sync(~0u, s_my, j);
            float exv = s_ex[w][j * 8 + hsel];
            float2 hv = *(const float2*)(h1c + (size_t)s * D1);
            accx = fmaf(hv.x, exv, accx);
            accy = fmaf(hv.y, exv, accy);
        }
        __syncwarp();
    }
#pragma unroll
    for (int h = 0; h < 8; h++) {
#pragma unroll
        for (int off = 16; off; off >>= 1)
            dsum[h] += __shfl_xor_sync(~0u, dsum[h], off);
    }
    float rc = 1.f / (dsum[hsel] + 1e-16f);
    float2 bb = *(const float2*)&b1[2 * lane];
    float h2x = elu1(fmaf(accx, rc, bb.x));
    float h2y = elu1(fmaf(accy, rc, bb.y));
    float p[C2];
#pragma unroll
    for (int c = 0; c < C2; c++)
        p[c] = fmaf(h2x, __ldg(&W2[(2 * lane) * C2 + c]),
               h2y * __ldg(&W2[(2 * lane + 1) * C2 + c]));
#pragma unroll
    for (int off = 16; off; off >>= 1)
#pragma unroll
        for (int c = 0; c < C2; c++) p[c] += __shfl_xor_sync(~0u, p[c], off);
    float al = 0.f, ar = 0.f;
#pragma unroll
    for (int c = 0; c < C2; c++) {
        al = fmaf(p[c], __ldg(&as2[c]), al);
        ar = fmaf(p[c], __ldg(&ad2[c]), ar);
    }
    if (lane == 0) { g_al2[d] = al; g_ar2[d] = ar; }
    if (lane < C2) {
        float v = p[0];
#pragma unroll
        for (int c = 1; c < C2; c++) if (lane == c) v = p[c];
        g_z2[d * C2 + lane] = v;
    }
}

// layer-2 aggregation + fused log_softmax; 4-way MLP unroll
__global__ void agg2_kernel(const float* __restrict__ b2, float* __restrict__ out) {
    int d = (blockIdx.x * blockDim.x + threadIdx.x) >> 5;
    int lane = threadIdx.x & 31;
    if (d >= NN) return;
    int beg = g_off[d], end = g_off[d + 1];
    float ard = g_ar2[d];
    float acc = 0.f, dsum = 0.f;
    bool cl = lane < C2;
    for (int b = beg; b < end; b += 32) {
        int n = min(32, end - b);
        int s_my = (b + lane < end) ? g_esrc[b + lane] : 0;
        float ex_my = (b + lane < end) ? fast_exp(lrelu(g_al2[s_my] + ard)) : 0.f;
        dsum += ex_my;
        int j = 0;
        for (; j + 4 <= n; j += 4) {
            int s0 = __shfl_sync(~0u, s_my, j);
            int s1 = __shfl_sync(~0u, s_my, j + 1);
            int s2 = __shfl_sync(~0u, s_my, j + 2);
            int s3 = __shfl_sync(~0u, s_my, j + 3);
            float e0 = __shfl_sync(~0u, ex_my, j);
            float e1 = __shfl_sync(~0u, ex_my, j + 1);
            float e2 = __shfl_sync(~0u, ex_my, j + 2);
            float e3 = __shfl_sync(~0u, ex_my, j + 3);
            float z0 = cl ? g_z2[s0 * C2 + lane] : 0.f;
            float z1 = cl ? g_z2[s1 * C2 + lane] : 0.f;
            float z2 = cl ? g_z2[s2 * C2 + lane] : 0.f;
            float z3 = cl ? g_z2[s3 * C2 + lane] : 0.f;
            acc = fmaf(z0, e0, acc);
            acc = fmaf(z1, e1, acc);
            acc = fmaf(z2, e2, acc);
            acc = fmaf(z3, e3, acc);
        }
        for (; j < n; j++) {
            int   s  = __shfl_sync(~0u, s_my, j);
            float ex = __shfl_sync(~0u, ex_my, j);
            if (cl) acc = fmaf(g_z2[s * C2 + lane], ex, acc);
        }
    }
#pragma unroll
    for (int off = 16; off; off >>= 1)
        dsum += __shfl_xor_sync(~0u, dsum, off);
    float rc = 1.f / (dsum + 1e-16f);
    float v = cl ? fmaf(acc, rc, __ldg(&b2[lane])) : -1e30f;
    float m = v;
#pragma unroll
    for (int off = 8; off; off >>= 1)
        m = fmaxf(m, __shfl_xor_sync(~0u, m, off, 16));
    float s = cl ? fast_exp(v - m) : 0.f;
#pragma unroll
    for (int off = 8; off; off >>= 1)
        s += __shfl_xor_sync(~0u, s, off, 16);
    float l = m + logf(s);
    if (cl) out[(size_t)d * C2 + lane] = v - l;
}

// ---------------- launch ----------------
extern "C" void kernel_launch(void* const* d_in, const int* in_sizes, int n_in,
                              void* d_out, int out_size) {
    const float* x   = (const float*)d_in[0];
    const int*   ei  = (const int*)d_in[1];    // int32 (JAX x64 disabled)
    const float* W1  = (const float*)d_in[2];
    const float* as1 = (const float*)d_in[3];
    const float* ad1 = (const float*)d_in[4];
    const float* b1  = (const float*)d_in[5];
    const float* W2  = (const float*)d_in[6];
    const float* as2 = (const float*)d_in[7];
    const float* ad2 = (const float*)d_in[8];
    const float* b2  = (const float*)d_in[9];

    int E = in_sizes[1] / 2;
    const int* src = ei;
    const int* dst = ei + E;
    int tot = E + NN;
    int nb1 = (NN + 1023) / 1024;

    bprep_kernel  <<<32, 256>>>(W1);                                    // 0
    hist_kernel   <<<(tot + 255) / 256, 256>>>(src, dst, E);            // 1
    scan1_kernel  <<<nb1, 1024>>>();                                    // 2
    gemm1_kernel  <<<(NN + 127) / 128, 256>>>(x, as1, ad1);             // 3 <- profiled
    scan23_kernel <<<nb1, 1024>>>(nb1);                                 // 4
    scatter_kernel<<<(tot + 255) / 256, 256>>>(src, dst, E);            // 5
    agg1_kernel   <<<(NN * 32 + 255) / 256, 256>>>(b1, W2, as2, ad2);   // 6
    agg2_kernel   <<<(NN * 32 + 255) / 256, 256>>>(b2, (float*)d_out);  // 7
}